// round 7
// baseline (speedup 1.0000x reference)
#include <cuda_runtime.h>
#include <cuda_bf16.h>

// ChannelPolyLayer: out[b,o,x,y] = sum_c coeffs[b,o,c] * prod_v img[b,v,x,y]^powers[c,v]
// DEGREE=3, NUM_VARS=3, NUM_OUT=3, NUM_COEFFS=20, BATCH=16, H=W=512.
//
// Monomial order from _generate_powers(3,3):
//  0:1  1:v0  2:v1  3:v2  4:v0^2  5:v0v1  6:v0v2  7:v1^2  8:v1v2  9:v2^2
// 10:v0^3 11:v0^2v1 12:v0^2v2 13:v0v1^2 14:v0v1v2 15:v0v2^2
// 16:v1^3 17:v1^2v2 18:v1v2^2 19:v2^3
//
// Nested Horner, packed fma.rn.f32x2 (19 per output per pixel-pair).
// R7: batch = blockIdx.y (no batch math in loop, 1-batch coeffs in smem),
// single-float4 items with 1-deep prefetch (MLP=3, 24 data regs),
// __launch_bounds__(256,3): 84-reg cap ABOVE natural demand (~74) ->
// 3 CTAs/SM = 24 warps without the R5 operand-pairing pathology.

#define HW_PIX (512 * 512)
#define PLANE4 (HW_PIX / 4)       // 65536 float4s per channel plane
#define NBATCH 16
#define NCOEF  20
#define CTAS_X 27                 // 27*16 = 432 CTAs ~= one wave at 3/SM
#define STRIDE (CTAS_X * 256)     // 6912

typedef unsigned long long ull;

__device__ __forceinline__ ull ffma2(ull a, ull b, ull c) {
    ull d;
    asm("fma.rn.f32x2 %0, %1, %2, %3;" : "=l"(d) : "l"(a), "l"(b), "l"(c));
    return d;
}

// Horner over a packed pair of pixels. c[] are {coeff,coeff} splat pairs.
__device__ __forceinline__ ull horner2(ull v0, ull v1, ull v2,
                                       const ull* __restrict__ c) {
    ull pA = ffma2(c[16], v1, c[7]);
    pA = ffma2(v1, pA, c[2]);
    pA = ffma2(v1, pA, c[0]);
    ull pB = ffma2(c[17], v1, c[8]);
    pB = ffma2(v1, pB, c[3]);
    ull pC = ffma2(c[18], v1, c[9]);
    ull C0 = ffma2(c[19], v2, pC);
    C0 = ffma2(C0, v2, pB);
    C0 = ffma2(C0, v2, pA);
    ull qA = ffma2(c[13], v1, c[5]);
    qA = ffma2(v1, qA, c[1]);
    ull qB = ffma2(c[14], v1, c[6]);
    ull C1 = ffma2(c[15], v2, qB);
    C1 = ffma2(C1, v2, qA);
    ull C2 = ffma2(c[11], v1, c[4]);
    C2 = ffma2(c[12], v2, C2);
    ull r = ffma2(c[10], v0, C2);
    r = ffma2(r, v0, C1);
    r = ffma2(r, v0, C0);
    return r;
}

__global__ __launch_bounds__(256, 3) void channel_poly_kernel(
    const float* __restrict__ img,     // (B, 3, H, W)
    const float* __restrict__ coeffs,  // (B, 3, 20)
    float* __restrict__ out)           // (B, 3, H, W)
{
    __shared__ ull sc2[3 * NCOEF];     // this batch's 60 splat pairs
    const int b = blockIdx.y;
    const int t = threadIdx.x;
    if (t < 3 * NCOEF) {
        ull u = (ull)__float_as_uint(coeffs[b * (3 * NCOEF) + t]);
        sc2[t] = u | (u << 32);        // splat {c, c}
    }
    __syncthreads();                   // the only barrier

    const ulonglong2* __restrict__ in =
        reinterpret_cast<const ulonglong2*>(img + (size_t)b * 3 * HW_PIX);
    ulonglong2* __restrict__ op =
        reinterpret_cast<ulonglong2*>(out + (size_t)b * 3 * HW_PIX);

    int i = blockIdx.x * 256 + t;      // < 6912 < PLANE4 always

    // Prefetch first item (3 LDG.128).
    ulonglong2 x0 = in[i], x1 = in[i + PLANE4], x2 = in[i + 2 * PLANE4];

#pragma unroll 1
    while (i < PLANE4) {
        // Issue next item's loads before computing this one.
        const int inext = i + STRIDE;
        const int il = (inext < PLANE4) ? inext : i;  // safe addr, result unused on tail
        const ulonglong2 n0 = in[il];
        const ulonglong2 n1 = in[il + PLANE4];
        const ulonglong2 n2 = in[il + 2 * PLANE4];

#pragma unroll 1
        for (int oc = 0; oc < 3; oc++) {
            const ull* __restrict__ c = sc2 + oc * NCOEF;
            ulonglong2 r;
            r.x = horner2(x0.x, x1.x, x2.x, c);
            r.y = horner2(x0.y, x1.y, x2.y, c);
            op[i + oc * PLANE4] = r;
        }

        i = inext;
        x0 = n0; x1 = n1; x2 = n2;
    }
}

extern "C" void kernel_launch(void* const* d_in, const int* in_sizes, int n_in,
                              void* d_out, int out_size) {
    const float* img = (const float*)d_in[0];     // (16,3,512,512)
    const float* coeffs = (const float*)d_in[1];  // (16,3,20)
    float* out = (float*)d_out;

    dim3 grid(CTAS_X, NBATCH, 1);                 // 432 CTAs
    channel_poly_kernel<<<grid, 256>>>(img, coeffs, out);
}

// round 8
// speedup vs baseline: 1.1054x; 1.1054x over previous
#include <cuda_runtime.h>
#include <cuda_bf16.h>

// ChannelPolyLayer: out[b,o,x,y] = sum_c coeffs[b,o,c] * prod_v img[b,v,x,y]^powers[c,v]
// DEGREE=3, NUM_VARS=3, NUM_OUT=3, NUM_COEFFS=20, BATCH=16, H=W=512.
//
// Monomial order from _generate_powers(3,3):
//  0:1  1:v0  2:v1  3:v2  4:v0^2  5:v0v1  6:v0v2  7:v1^2  8:v1v2  9:v2^2
// 10:v0^3 11:v0^2v1 12:v0^2v2 13:v0v1^2 14:v0v1v2 15:v0v2^2
// 16:v1^3 17:v1^2v2 18:v1v2^2 19:v2^3
//
// Nested Horner, packed fma.rn.f32x2 (19 per output per pixel-pair).
// R8: max out per-SM outstanding loads (the only lever that has moved this
// kernel): 4 float4 items/thread, all 12 LDG.128 front-batched (MLP_p1=12),
// 128-thread CTAs, __launch_bounds__(128,5) -> 20 warps/SM * 12 = 240
// loads in flight (2x R4). batch = blockIdx.y (no batch math). No loop,
// exact partition (65536 = 4 * 128 * 128), no tail.

#define HW_PIX (512 * 512)
#define PLANE4 (HW_PIX / 4)       // 65536 float4s per channel plane
#define NBATCH 16
#define NCOEF  20
#define TPB    128
#define QUART  (PLANE4 / 4)       // 16384: item j lives at i + j*QUART
#define CTAS_X (PLANE4 / (4 * TPB))  // 128

typedef unsigned long long ull;

__device__ __forceinline__ ull ffma2(ull a, ull b, ull c) {
    ull d;
    asm("fma.rn.f32x2 %0, %1, %2, %3;" : "=l"(d) : "l"(a), "l"(b), "l"(c));
    return d;
}

// Horner over a packed pair of pixels. c[] are {coeff,coeff} splat pairs.
__device__ __forceinline__ ull horner2(ull v0, ull v1, ull v2,
                                       const ull* __restrict__ c) {
    ull pA = ffma2(c[16], v1, c[7]);
    pA = ffma2(v1, pA, c[2]);
    pA = ffma2(v1, pA, c[0]);
    ull pB = ffma2(c[17], v1, c[8]);
    pB = ffma2(v1, pB, c[3]);
    ull pC = ffma2(c[18], v1, c[9]);
    ull C0 = ffma2(c[19], v2, pC);
    C0 = ffma2(C0, v2, pB);
    C0 = ffma2(C0, v2, pA);
    ull qA = ffma2(c[13], v1, c[5]);
    qA = ffma2(v1, qA, c[1]);
    ull qB = ffma2(c[14], v1, c[6]);
    ull C1 = ffma2(c[15], v2, qB);
    C1 = ffma2(C1, v2, qA);
    ull C2 = ffma2(c[11], v1, c[4]);
    C2 = ffma2(c[12], v2, C2);
    ull r = ffma2(c[10], v0, C2);
    r = ffma2(r, v0, C1);
    r = ffma2(r, v0, C0);
    return r;
}

__global__ __launch_bounds__(TPB, 5) void channel_poly_kernel(
    const float* __restrict__ img,     // (B, 3, H, W)
    const float* __restrict__ coeffs,  // (B, 3, 20)
    float* __restrict__ out)           // (B, 3, H, W)
{
    __shared__ ull sc2[3 * NCOEF];     // this batch's 60 splat pairs
    const int b = blockIdx.y;
    const int t = threadIdx.x;
    if (t < 3 * NCOEF) {
        ull u = (ull)__float_as_uint(coeffs[b * (3 * NCOEF) + t]);
        sc2[t] = u | (u << 32);        // splat {c, c}
    }
    __syncthreads();

    const int i = blockIdx.x * TPB + t;   // 0..16383

    const ulonglong2* __restrict__ in =
        reinterpret_cast<const ulonglong2*>(img + (size_t)b * 3 * HW_PIX);
    ulonglong2* __restrict__ op =
        reinterpret_cast<ulonglong2*>(out + (size_t)b * 3 * HW_PIX);

    // Front-batch all 12 LDG.128 (MLP_p1 = 12).
    const ulonglong2 a0 = in[i];
    const ulonglong2 a1 = in[i + PLANE4];
    const ulonglong2 a2 = in[i + 2 * PLANE4];
    const ulonglong2 b0 = in[i + QUART];
    const ulonglong2 b1 = in[i + QUART + PLANE4];
    const ulonglong2 b2 = in[i + QUART + 2 * PLANE4];
    const ulonglong2 c0 = in[i + 2 * QUART];
    const ulonglong2 c1 = in[i + 2 * QUART + PLANE4];
    const ulonglong2 c2 = in[i + 2 * QUART + 2 * PLANE4];
    const ulonglong2 d0 = in[i + 3 * QUART];
    const ulonglong2 d1 = in[i + 3 * QUART + PLANE4];
    const ulonglong2 d2 = in[i + 3 * QUART + 2 * PLANE4];

#pragma unroll 1
    for (int oc = 0; oc < 3; oc++) {
        const ull* __restrict__ c = sc2 + oc * NCOEF;
        ulonglong2 ra, rb, rc, rd;
        ra.x = horner2(a0.x, a1.x, a2.x, c);
        ra.y = horner2(a0.y, a1.y, a2.y, c);
        rb.x = horner2(b0.x, b1.x, b2.x, c);
        rb.y = horner2(b0.y, b1.y, b2.y, c);
        rc.x = horner2(c0.x, c1.x, c2.x, c);
        rc.y = horner2(c0.y, c1.y, c2.y, c);
        rd.x = horner2(d0.x, d1.x, d2.x, c);
        rd.y = horner2(d0.y, d1.y, d2.y, c);
        op[i + oc * PLANE4] = ra;
        op[i + QUART + oc * PLANE4] = rb;
        op[i + 2 * QUART + oc * PLANE4] = rc;
        op[i + 3 * QUART + oc * PLANE4] = rd;
    }
}

extern "C" void kernel_launch(void* const* d_in, const int* in_sizes, int n_in,
                              void* d_out, int out_size) {
    const float* img = (const float*)d_in[0];     // (16,3,512,512)
    const float* coeffs = (const float*)d_in[1];  // (16,3,20)
    float* out = (float*)d_out;

    dim3 grid(CTAS_X, NBATCH, 1);                 // 128 x 16 = 2048 CTAs
    channel_poly_kernel<<<grid, TPB>>>(img, coeffs, out);
}